// round 7
// baseline (speedup 1.0000x reference)
#include <cuda_runtime.h>

#define HH 512
#define WW 512
#define NPIX (HH*WW)
#define NIMG 32
#define SMOOTHF 1e-5f
#define HALO_C 12       // column halo per side (= 2*K1, multiple of 4)
#define OWNC 104        // owned columns per warp window (128 - 2*HALO_C)
#define CTILES 5        // ceil(512/104)
#define RB 128          // rows per band
#define NBANDS 4
#define ALLM 0xffffffffu

// Scratch (device globals: no allocation allowed; zero-initialized at load)
__device__ float g_tmp[2][NIMG*NPIX];    // after pass-1 iterations
__device__ float g_acc[NIMG][8];         // 0:sp 1:st 2:spt 3:ssp 4:sst 5:sspt

__device__ __forceinline__ float sigf(float x){
    return __fdividef(1.0f, 1.0f + __expf(-x));
}

// Load one float4 row segment (PINF sentinel outside image); optional sigmoid.
__device__ __forceinline__ void fetch_row(float (&d)[4], const float* __restrict__ src,
                                          int row, int gc, bool colok, bool dosig,
                                          float PINF){
    if (colok && (unsigned)row < (unsigned)HH){
        float4 t4 = *(const float4*)(src + (size_t)row*WW + gc);
        if (dosig){
            t4.x = sigf(t4.x); t4.y = sigf(t4.y);
            t4.z = sigf(t4.z); t4.w = sigf(t4.w);
        }
        d[0]=t4.x; d[1]=t4.y; d[2]=t4.z; d[3]=t4.w;
    } else {
        d[0]=PINF; d[1]=PINF; d[2]=PINF; d[3]=PINF;
    }
}

// One decoupled pipeline stage. Fed row xr (value in cin). State:
// sN = In[xr-1], sO = In[xr-2], eN = E[xr-2], eO = E[xr-3].
// Computes E[xr-1] and O[xr-2] -> out. Rotation by role swap (zero MOVs).
// Output NOT boundary-forced: OOB it becomes +INF/NaN, and fminf/fmaxf drop
// NaN operands so downstream min chains treat it as the +INF sentinel.
// Only the eroded field is forced (-INF at OOB): it feeds a max-pool.
__device__ __forceinline__ void stage_one(
    float (&sN)[4], float (&sO)[4], float (&eN)[4], float (&eO)[4],
    const float (&cin)[4], float (&out)[4],
    int xr, bool colok, float NINF)
{
    float vm0 = fminf(sO[0], fminf(sN[0], cin[0]));
    float vm1 = fminf(sO[1], fminf(sN[1], cin[1]));
    float vm2 = fminf(sO[2], fminf(sN[2], cin[2]));
    float vm3 = fminf(sO[3], fminf(sN[3], cin[3]));
    float Lm = __shfl_up_sync  (ALLM, vm3, 1);
    float Rm = __shfl_down_sync(ALLM, vm0, 1);
    float m01 = fminf(vm0, vm1), m12 = fminf(vm1, vm2), m23 = fminf(vm2, vm3);
    float en0 = fminf(Lm,  m01);
    float en1 = fminf(m01, vm2);
    float en2 = fminf(m12, vm3);
    float en3 = fminf(m23, Rm);
    if (!(colok && (unsigned)(xr - 1) < (unsigned)HH)){
        en0 = NINF; en1 = NINF; en2 = NINF; en3 = NINF;
    }
    float tx0 = fmaxf(eO[0], fmaxf(eN[0], en0));
    float tx1 = fmaxf(eO[1], fmaxf(eN[1], en1));
    float tx2 = fmaxf(eO[2], fmaxf(eN[2], en2));
    float tx3 = fmaxf(eO[3], fmaxf(eN[3], en3));
    float Lx = __shfl_up_sync  (ALLM, tx3, 1);
    float Rx = __shfl_down_sync(ALLM, tx0, 1);
    float M01 = fmaxf(tx0, tx1), M12 = fmaxf(tx1, tx2), M23 = fmaxf(tx2, tx3);
    float T0 = fmaxf(Lx,  M01);
    float T1 = fmaxf(M01, tx2);
    float T2 = fmaxf(M12, tx3);
    float T3 = fmaxf(M23, Rx);
    float o0 = fmaf(eN[0]-sO[0], T0, sO[0]);
    float o1 = fmaf(eN[1]-sO[1], T1, sO[1]);
    float o2 = fmaf(eN[2]-sO[2], T2, sO[2]);
    float o3 = fmaf(eN[3]-sO[3], T3, sO[3]);
    sO[0]=cin[0]; sO[1]=cin[1]; sO[2]=cin[2]; sO[3]=cin[3];
    eO[0]=en0;    eO[1]=en1;    eO[2]=en2;    eO[3]=en3;
    out[0]=o0; out[1]=o1; out[2]=o2; out[3]=o3;
}

// K decoupled stages, evaluated in DESCENDING order so each stage j+1 reads
// buf[j] (previous step's output of stage j) before stage j overwrites it.
// All K stages mutually independent within a step -> ILP ~K.
template<int K>
__device__ __forceinline__ void pipe_step(
    float (&sN)[K][4], float (&sO)[K][4], float (&eN)[K][4], float (&eO)[K][4],
    float (&buf)[K][4], const float (&in0)[4], float (&out)[4],
    int x, bool colok, float NINF)
{
    stage_one(sN[K-1], sO[K-1], eN[K-1], eO[K-1], buf[K-2], out, x - 3*(K-1), colok, NINF);
    #pragma unroll
    for (int j = K-2; j >= 1; j--)
        stage_one(sN[j], sO[j], eN[j], eO[j], buf[j-1], buf[j], x - 3*j, colok, NINF);
    stage_one(sN[0], sO[0], eN[0], eO[0], in0, buf[0], x, colok, NINF);
}

template<int K>
__device__ __forceinline__ void pipe_init(
    float (&sA)[K][4], float (&sB)[K][4], float (&eA)[K][4], float (&eB)[K][4],
    float (&buf)[K][4], float (&nxt)[4], float PINF, float NINF)
{
    #pragma unroll
    for (int j = 0; j < K; j++)
        #pragma unroll
        for (int v = 0; v < 4; v++){
            sA[j][v]=PINF; sB[j][v]=PINF; eA[j][v]=NINF; eB[j][v]=NINF; buf[j][v]=PINF;
        }
    #pragma unroll
    for (int v = 0; v < 4; v++) nxt[v]=PINF;
}

// ---------------- pass 1: iterations 1..K1, fused plain-dice sums ----------
template<int K>
__global__ void __launch_bounds__(32) k_skel1(const float* __restrict__ logits,
                                              const float* __restrict__ target){
    const float PINF = __int_as_float(0x7f800000);
    const float NINF = __int_as_float(0xff800000);
    constexpr int LAGOUT = 3*(K-1)+2;
    constexpr int X0OFF  = 2*K+1;
    constexpr int NSTEPS = RB + 5*K;      // = RB + LAGOUT + X0OFF (even)

    int gw = blockIdx.x, lane = threadIdx.x;
    int band = gw & 3; int q = gw >> 2;
    int ct = q % CTILES; q /= CTILES;
    int img = q & 31; int tens = q >> 5;
    bool dosig = (tens == 0);

    const float* __restrict__ src = (tens ? target : logits) + (size_t)img*NPIX;
    const float* __restrict__ tg  = target + (size_t)img*NPIX;
    float* __restrict__ dst = g_tmp[tens] + (size_t)img*NPIX;

    int r0 = band*RB;
    int gc = ct*OWNC - HALO_C + (lane<<2);
    bool colok = (gc >= 0) && (gc < WW);
    bool owned = (lane >= HALO_C/4) && (lane < (HALO_C+OWNC)/4) && colok;

    float sA[K][4], sB[K][4], eA[K][4], eB[K][4], buf[K][4], nxt[4];
    pipe_init<K>(sA,sB,eA,eB,buf,nxt,PINF,NINF);

    int x0 = r0 - X0OFF;
    fetch_row(nxt, src, x0, gc, colok, dosig, PINF);

    float ap=0.f, at=0.f, apt=0.f;

#define STEP1(X, SN, SO, EN, EO)                                              \
{                                                                             \
    int x = (X);                                                              \
    float in0[4] = {nxt[0], nxt[1], nxt[2], nxt[3]};                          \
    int xn = x + 1;                                                           \
    fetch_row(nxt, src, xn, gc, colok, dosig, PINF);                          \
    if (dosig && owned && (unsigned)(xn - r0) < (unsigned)RB){                \
        float4 t4 = *(const float4*)(tg + (size_t)xn*WW + gc);                \
        ap  += (nxt[0]+nxt[1]) + (nxt[2]+nxt[3]);                             \
        at  += (t4.x+t4.y) + (t4.z+t4.w);                                     \
        apt += (nxt[0]*t4.x + nxt[1]*t4.y) + (nxt[2]*t4.z + nxt[3]*t4.w);     \
    }                                                                         \
    float o4[4];                                                              \
    pipe_step<K>(SN, SO, EN, EO, buf, in0, o4, x, colok, NINF);               \
    if (owned && (unsigned)(x - LAGOUT - r0) < (unsigned)RB){                 \
        *(float4*)(dst + (size_t)(x - LAGOUT)*WW + gc) =                      \
            make_float4(o4[0], o4[1], o4[2], o4[3]);                          \
    }                                                                         \
}
    for (int s = 0; s < NSTEPS; s += 2){
        STEP1(x0 + s,     sA, sB, eA, eB);
        STEP1(x0 + s + 1, sB, sA, eB, eA);
    }
#undef STEP1

    if (dosig){
        #pragma unroll
        for (int o=16;o;o>>=1){
            ap  += __shfl_down_sync(ALLM, ap , o);
            at  += __shfl_down_sync(ALLM, at , o);
            apt += __shfl_down_sync(ALLM, apt, o);
        }
        if (lane == 0){
            atomicAdd(&g_acc[img][0], ap);
            atomicAdd(&g_acc[img][1], at);
            atomicAdd(&g_acc[img][2], apt);
        }
    }
}

// ---------------- pass 2: iterations K1+1..10 for BOTH tensors per warp, ----
// ---------------- fused skeleton-dice sums, zero stores ---------------------
template<int K>
__global__ void __launch_bounds__(32) k_skel2(){
    const float PINF = __int_as_float(0x7f800000);
    const float NINF = __int_as_float(0xff800000);
    constexpr int LAGOUT = 3*(K-1)+2;
    constexpr int X0OFF  = 2*K+1;
    constexpr int NSTEPS = RB + 5*K;

    int gw = blockIdx.x, lane = threadIdx.x;
    int band = gw & 3; int q = gw >> 2;
    int ct = q % CTILES;
    int img = q / CTILES;

    const float* __restrict__ srcP = g_tmp[0] + (size_t)img*NPIX;
    const float* __restrict__ srcT = g_tmp[1] + (size_t)img*NPIX;

    int r0 = band*RB;
    int gc = ct*OWNC - HALO_C + (lane<<2);
    bool colok = (gc >= 0) && (gc < WW);
    bool owned = (lane >= HALO_C/4) && (lane < (HALO_C+OWNC)/4) && colok;

    float sAP[K][4], sBP[K][4], eAP[K][4], eBP[K][4], bufP[K][4], nxP[4];
    float sAT[K][4], sBT[K][4], eAT[K][4], eBT[K][4], bufT[K][4], nxT[4];
    pipe_init<K>(sAP,sBP,eAP,eBP,bufP,nxP,PINF,NINF);
    pipe_init<K>(sAT,sBT,eAT,eBT,bufT,nxT,PINF,NINF);

    int x0 = r0 - X0OFF;
    fetch_row(nxP, srcP, x0, gc, colok, false, PINF);
    fetch_row(nxT, srcT, x0, gc, colok, false, PINF);

    float sp=0.f, st=0.f, spt=0.f;

#define STEP2(X, SNP, SOP, ENP, EOP, SNT, SOT, ENT, EOT)                      \
{                                                                             \
    int x = (X);                                                              \
    float inP[4] = {nxP[0], nxP[1], nxP[2], nxP[3]};                          \
    float inT[4] = {nxT[0], nxT[1], nxT[2], nxT[3]};                          \
    fetch_row(nxP, srcP, x+1, gc, colok, false, PINF);                        \
    fetch_row(nxT, srcT, x+1, gc, colok, false, PINF);                        \
    float oP[4], oT[4];                                                       \
    pipe_step<K>(SNP, SOP, ENP, EOP, bufP, inP, oP, x, colok, NINF);          \
    pipe_step<K>(SNT, SOT, ENT, EOT, bufT, inT, oT, x, colok, NINF);          \
    if (owned && (unsigned)(x - LAGOUT - r0) < (unsigned)RB){                 \
        sp  += (oP[0]+oP[1]) + (oP[2]+oP[3]);                                 \
        st  += (oT[0]+oT[1]) + (oT[2]+oT[3]);                                 \
        spt += (oP[0]*oT[0] + oP[1]*oT[1]) + (oP[2]*oT[2] + oP[3]*oT[3]);     \
    }                                                                         \
}
    for (int s = 0; s < NSTEPS; s += 2){
        STEP2(x0 + s,     sAP, sBP, eAP, eBP, sAT, sBT, eAT, eBT);
        STEP2(x0 + s + 1, sBP, sAP, eBP, eAP, sBT, sAT, eBT, eAT);
    }
#undef STEP2

    #pragma unroll
    for (int o=16;o;o>>=1){
        sp  += __shfl_down_sync(ALLM, sp , o);
        st  += __shfl_down_sync(ALLM, st , o);
        spt += __shfl_down_sync(ALLM, spt, o);
    }
    if (lane == 0){
        atomicAdd(&g_acc[img][3], sp);
        atomicAdd(&g_acc[img][4], st);
        atomicAdd(&g_acc[img][5], spt);
    }
}

// ---------------- final reduction (also re-zeroes accumulators) -------------
__global__ void k_fin(float* __restrict__ out){
    int i = threadIdx.x;   // 32 threads, one per image
    float d  = (2.0f*g_acc[i][2] + SMOOTHF) / (g_acc[i][0] + g_acc[i][1] + SMOOTHF);
    float sd = (2.0f*g_acc[i][5] + SMOOTHF) / (g_acc[i][3] + g_acc[i][4] + SMOOTHF);
    #pragma unroll
    for (int o=16;o;o>>=1){
        d  += __shfl_down_sync(ALLM, d , o);
        sd += __shfl_down_sync(ALLM, sd, o);
    }
    if (i == 0){
        float dice  = d  * (1.0f/32.0f);
        float sdice = sd * (1.0f/32.0f);
        out[0] = 0.5f*(1.0f - dice) + 0.5f*(1.0f - sdice);
        out[1] = dice;
        out[2] = sdice;
    }
    // reset accumulators for the next graph replay (globals start zeroed at
    // module load, so the invariant "g_acc == 0 on entry" always holds)
    #pragma unroll
    for (int v = 0; v < 8; v++) g_acc[i][v] = 0.0f;
}

extern "C" void kernel_launch(void* const* d_in, const int* in_sizes, int n_in,
                              void* d_out, int out_size){
    const float* logits = (const float*)d_in[0];
    const float* target = (const float*)d_in[1];
    float* out = (float*)d_out;

    int nblk1 = 2 * NIMG * CTILES * NBANDS;   // 1280 single-warp blocks
    int nblk2 =     NIMG * CTILES * NBANDS;   // 640  single-warp blocks

    k_skel1<6><<<nblk1, 32>>>(logits, target);   // iters 1..6 + dice sums
    k_skel2<4><<<nblk2, 32>>>();                 // iters 7..10 + skel-dice sums
    k_fin<<<1, 32>>>(out);
    (void)in_sizes; (void)n_in; (void)out_size;
}

// round 8
// speedup vs baseline: 1.1601x; 1.1601x over previous
#include <cuda_runtime.h>

#define HH 512
#define WW 512
#define NPIX (HH*WW)
#define NIMG 32
#define SMOOTHF 1e-5f
#define KF 5            // fused skeletonize iterations per pass
#define HALO_C 12       // column halo per side (>= 2*KF, multiple of 4)
#define OWNC 104        // owned columns per warp window (128 - 2*HALO_C)
#define CTILES 5        // ceil(512/104)
#define RB 128          // rows per band
#define NBANDS 4
#define LAGOUT 14       // output lag: 3*(KF-1)+2
#define NSTEPS 154      // RB + 25 + 1 (even, x0 = r0-11)
#define ALLM 0xffffffffu

// Scratch (device globals: no allocation allowed; zero-initialized at load)
__device__ float g_tmp [2][NIMG*NPIX];   // after iterations 1..5
__device__ float g_skel[2][NIMG*NPIX];   // after iterations 6..10
__device__ float g_acc [NIMG][8];        // 0:sp 1:st 2:spt 3:ssp 4:sst 5:sspt

__device__ __forceinline__ float sigf(float x){
    return __fdividef(1.0f, 1.0f + __expf(-x));
}

// One decoupled pipeline stage j. Fed row xr = x - 3j (value in CIN).
// State: sN[j] = In_j[xr-1], sO[j] = In_j[xr-2], eN[j] = E_j[xr-2],
// eO[j] = E_j[xr-3]. Computes E_j[xr-1] and O_j[xr-2] -> OUT.
// Rotation by role swap (zero MOVs). Output is NOT boundary-forced: at OOB
// it becomes +INF or NaN; fminf/fmaxf drop NaN operands, so downstream min
// chains treat it exactly as the +INF sentinel. Only the eroded field is
// forced (-INF at OOB) since it feeds a max-pool.
#define STAGE(j, sN, sO, eN, eO, CIN, OUT)                                    \
{                                                                             \
    float vm0 = fminf(sO[j][0], fminf(sN[j][0], CIN[0]));                     \
    float vm1 = fminf(sO[j][1], fminf(sN[j][1], CIN[1]));                     \
    float vm2 = fminf(sO[j][2], fminf(sN[j][2], CIN[2]));                     \
    float vm3 = fminf(sO[j][3], fminf(sN[j][3], CIN[3]));                     \
    float Lm = __shfl_up_sync  (ALLM, vm3, 1);                                \
    float Rm = __shfl_down_sync(ALLM, vm0, 1);                                \
    float m01 = fminf(vm0, vm1), m12 = fminf(vm1, vm2), m23 = fminf(vm2, vm3);\
    float en0 = fminf(Lm,  m01);                                              \
    float en1 = fminf(m01, vm2);                                              \
    float en2 = fminf(m12, vm3);                                              \
    float en3 = fminf(m23, Rm);                                               \
    if (!(colok && (unsigned)(x - 3*(j) - 1) < (unsigned)HH)){                \
        en0 = NINF; en1 = NINF; en2 = NINF; en3 = NINF;                       \
    }                                                                         \
    float tx0 = fmaxf(eO[j][0], fmaxf(eN[j][0], en0));                        \
    float tx1 = fmaxf(eO[j][1], fmaxf(eN[j][1], en1));                        \
    float tx2 = fmaxf(eO[j][2], fmaxf(eN[j][2], en2));                        \
    float tx3 = fmaxf(eO[j][3], fmaxf(eN[j][3], en3));                        \
    float Lx = __shfl_up_sync  (ALLM, tx3, 1);                                \
    float Rx = __shfl_down_sync(ALLM, tx0, 1);                                \
    float M01 = fmaxf(tx0, tx1), M12 = fmaxf(tx1, tx2), M23 = fmaxf(tx2, tx3);\
    float T0 = fmaxf(Lx,  M01);                                               \
    float T1 = fmaxf(M01, tx2);                                               \
    float T2 = fmaxf(M12, tx3);                                               \
    float T3 = fmaxf(M23, Rx);                                                \
    float o0 = fmaf(eN[j][0]-sO[j][0], T0, sO[j][0]);                         \
    float o1 = fmaf(eN[j][1]-sO[j][1], T1, sO[j][1]);                         \
    float o2 = fmaf(eN[j][2]-sO[j][2], T2, sO[j][2]);                         \
    float o3 = fmaf(eN[j][3]-sO[j][3], T3, sO[j][3]);                         \
    sO[j][0] = CIN[0]; sO[j][1] = CIN[1]; sO[j][2] = CIN[2]; sO[j][3] = CIN[3];\
    eO[j][0] = en0;    eO[j][1] = en1;    eO[j][2] = en2;    eO[j][3] = en3;  \
    OUT[0] = o0; OUT[1] = o1; OUT[2] = o2; OUT[3] = o3;                       \
}

// One full row-step. Stages evaluated in DESCENDING order so each stage j+1
// reads buf[j] (previous step's output of stage j) before stage j overwrites
// it. All 5 stages are mutually independent within a step -> ILP ~5.
// DICE: if nonzero, accumulate plain-dice sums on the freshly fetched row.
#define DO_STEP(X, sN, sO, eN, eO, DOSIG, DICE)                               \
{                                                                             \
    int x = (X);                                                              \
    float in0[4] = {nxt[0], nxt[1], nxt[2], nxt[3]};                          \
    int xn = x + 1;                                                           \
    if (colok && (unsigned)xn < (unsigned)HH){                                \
        float4 t4 = *(const float4*)(src + (size_t)xn*WW + gc);               \
        if (DOSIG){                                                           \
            t4.x = sigf(t4.x); t4.y = sigf(t4.y);                             \
            t4.z = sigf(t4.z); t4.w = sigf(t4.w);                             \
        }                                                                     \
        nxt[0]=t4.x; nxt[1]=t4.y; nxt[2]=t4.z; nxt[3]=t4.w;                   \
    } else {                                                                  \
        nxt[0]=PINF; nxt[1]=PINF; nxt[2]=PINF; nxt[3]=PINF;                   \
    }                                                                         \
    if (DICE){                                                                \
        if ((DOSIG) && owned && (unsigned)(xn - r0) < (unsigned)RB){          \
            float4 tt = *(const float4*)(tg + (size_t)xn*WW + gc);            \
            ap  += (nxt[0]+nxt[1]) + (nxt[2]+nxt[3]);                         \
            at  += (tt.x+tt.y) + (tt.z+tt.w);                                 \
            apt += (nxt[0]*tt.x + nxt[1]*tt.y) + (nxt[2]*tt.z + nxt[3]*tt.w); \
        }                                                                     \
    }                                                                         \
    float o4[4];                                                              \
    STAGE(4, sN, sO, eN, eO, b3,  o4);                                        \
    STAGE(3, sN, sO, eN, eO, b2,  b3);                                        \
    STAGE(2, sN, sO, eN, eO, b1,  b2);                                        \
    STAGE(1, sN, sO, eN, eO, b0,  b1);                                        \
    STAGE(0, sN, sO, eN, eO, in0, b0);                                        \
    if (owned && (unsigned)(x - LAGOUT - r0) < (unsigned)RB){                 \
        *(float4*)(dst + (size_t)(x - LAGOUT)*WW + gc) =                      \
            make_float4(o4[0], o4[1], o4[2], o4[3]);                          \
    }                                                                         \
}

// ---------------- pass 1: iterations 1..5 + fused plain-dice sums ----------
__global__ void __launch_bounds__(32, 11) k_skel1(const float* __restrict__ logits,
                                                  const float* __restrict__ target){
    const float PINF = __int_as_float(0x7f800000);
    const float NINF = __int_as_float(0xff800000);

    int gw   = blockIdx.x;
    int lane = threadIdx.x;
    int band = gw & 3;  int q = gw >> 2;
    int ct   = q % CTILES; q /= CTILES;
    int img  = q & 31;  int tens = q >> 5;
    bool dosig = (tens == 0);

    const float* __restrict__ src = (tens ? target : logits) + (size_t)img*NPIX;
    const float* __restrict__ tg  = target + (size_t)img*NPIX;
    float* __restrict__ dst = g_tmp[tens] + (size_t)img*NPIX;

    int r0 = band * RB;
    int gc = ct*OWNC - HALO_C + (lane<<2);
    bool colok = (gc >= 0) && (gc < WW);
    bool owned = (lane >= HALO_C/4) && (lane < (HALO_C+OWNC)/4) && colok;

    float sA[KF][4], sB[KF][4], eA[KF][4], eB[KF][4];
    float b0[4], b1[4], b2[4], b3[4];
    #pragma unroll
    for (int j = 0; j < KF; j++)
        #pragma unroll
        for (int v = 0; v < 4; v++){
            sA[j][v]=PINF; sB[j][v]=PINF; eA[j][v]=NINF; eB[j][v]=NINF;
        }
    #pragma unroll
    for (int v = 0; v < 4; v++){ b0[v]=PINF; b1[v]=PINF; b2[v]=PINF; b3[v]=PINF; }

    int x0 = r0 - 11;
    float nxt[4];
    if (colok && (unsigned)x0 < (unsigned)HH){
        float4 t4 = *(const float4*)(src + (size_t)x0*WW + gc);
        if (dosig){
            t4.x = sigf(t4.x); t4.y = sigf(t4.y);
            t4.z = sigf(t4.z); t4.w = sigf(t4.w);
        }
        nxt[0]=t4.x; nxt[1]=t4.y; nxt[2]=t4.z; nxt[3]=t4.w;
    } else {
        nxt[0]=PINF; nxt[1]=PINF; nxt[2]=PINF; nxt[3]=PINF;
    }

    float ap=0.f, at=0.f, apt=0.f;

    for (int step = 0; step < NSTEPS; step += 2){
        DO_STEP(x0 + step,     sA, sB, eA, eB, dosig, 1);
        DO_STEP(x0 + step + 1, sB, sA, eB, eA, dosig, 1);
    }

    if (dosig){
        #pragma unroll
        for (int o=16;o;o>>=1){
            ap  += __shfl_down_sync(ALLM, ap , o);
            at  += __shfl_down_sync(ALLM, at , o);
            apt += __shfl_down_sync(ALLM, apt, o);
        }
        if (lane == 0){
            atomicAdd(&g_acc[img][0], ap);
            atomicAdd(&g_acc[img][1], at);
            atomicAdd(&g_acc[img][2], apt);
        }
    }
}

// ---------------- pass 2: iterations 6..10 (proven R6 body) ----------------
__global__ void __launch_bounds__(32, 12) k_skel2(){
    const float PINF = __int_as_float(0x7f800000);
    const float NINF = __int_as_float(0xff800000);

    int gw   = blockIdx.x;
    int lane = threadIdx.x;
    int band = gw & 3;  int q = gw >> 2;
    int ct   = q % CTILES; q /= CTILES;
    int img  = q & 31;  int tens = q >> 5;

    const float* __restrict__ src = g_tmp[tens] + (size_t)img*NPIX;
    float* __restrict__ dst = g_skel[tens] + (size_t)img*NPIX;
    const float* __restrict__ tg  = src;  // unused (DICE=0)

    int r0 = band * RB;
    int gc = ct*OWNC - HALO_C + (lane<<2);
    bool colok = (gc >= 0) && (gc < WW);
    bool owned = (lane >= HALO_C/4) && (lane < (HALO_C+OWNC)/4) && colok;

    float sA[KF][4], sB[KF][4], eA[KF][4], eB[KF][4];
    float b0[4], b1[4], b2[4], b3[4];
    #pragma unroll
    for (int j = 0; j < KF; j++)
        #pragma unroll
        for (int v = 0; v < 4; v++){
            sA[j][v]=PINF; sB[j][v]=PINF; eA[j][v]=NINF; eB[j][v]=NINF;
        }
    #pragma unroll
    for (int v = 0; v < 4; v++){ b0[v]=PINF; b1[v]=PINF; b2[v]=PINF; b3[v]=PINF; }

    int x0 = r0 - 11;
    float nxt[4];
    if (colok && (unsigned)x0 < (unsigned)HH){
        float4 t4 = *(const float4*)(src + (size_t)x0*WW + gc);
        nxt[0]=t4.x; nxt[1]=t4.y; nxt[2]=t4.z; nxt[3]=t4.w;
    } else {
        nxt[0]=PINF; nxt[1]=PINF; nxt[2]=PINF; nxt[3]=PINF;
    }

    float ap=0.f, at=0.f, apt=0.f; (void)ap; (void)at; (void)apt; (void)tg;

    for (int step = 0; step < NSTEPS; step += 2){
        DO_STEP(x0 + step,     sA, sB, eA, eB, 0, 0);
        DO_STEP(x0 + step + 1, sB, sA, eB, eA, 0, 0);
    }
}

// ---------------- skeleton dice sums (MLP-batched loads) ----------------
__global__ void k_sdice(){
    int img = blockIdx.x;
    size_t base = (size_t)img*NPIX + (size_t)blockIdx.y*(NPIX/32);
    const float4* Pp = (const float4*)(g_skel[0] + base);
    const float4* Tp = (const float4*)(g_skel[1] + base);
    int tid = threadIdx.x;
    // batch all 16 independent LDG.128 up front for max MLP
    float4 p[8], t[8];
    #pragma unroll
    for (int i = 0; i < 8; i++) p[i] = Pp[i*256 + tid];
    #pragma unroll
    for (int i = 0; i < 8; i++) t[i] = Tp[i*256 + tid];
    float sp=0.f, st=0.f, spt=0.f;
    #pragma unroll
    for (int i = 0; i < 8; i++){
        sp  += (p[i].x+p[i].y)+(p[i].z+p[i].w);
        st  += (t[i].x+t[i].y)+(t[i].z+t[i].w);
        spt += (p[i].x*t[i].x + p[i].y*t[i].y) + (p[i].z*t[i].z + p[i].w*t[i].w);
    }
    #pragma unroll
    for (int o=16;o;o>>=1){
        sp  += __shfl_down_sync(ALLM, sp , o);
        st  += __shfl_down_sync(ALLM, st , o);
        spt += __shfl_down_sync(ALLM, spt, o);
    }
    if ((tid & 31) == 0){
        atomicAdd(&g_acc[img][3], sp);
        atomicAdd(&g_acc[img][4], st);
        atomicAdd(&g_acc[img][5], spt);
    }
}

// ---------------- final reduction (also re-zeroes accumulators) -------------
__global__ void k_fin(float* __restrict__ out){
    int i = threadIdx.x;   // 32 threads, one per image
    float d  = (2.0f*g_acc[i][2] + SMOOTHF) / (g_acc[i][0] + g_acc[i][1] + SMOOTHF);
    float sd = (2.0f*g_acc[i][5] + SMOOTHF) / (g_acc[i][3] + g_acc[i][4] + SMOOTHF);
    #pragma unroll
    for (int o=16;o;o>>=1){
        d  += __shfl_down_sync(ALLM, d , o);
        sd += __shfl_down_sync(ALLM, sd, o);
    }
    if (i == 0){
        float dice  = d  * (1.0f/32.0f);
        float sdice = sd * (1.0f/32.0f);
        out[0] = 0.5f*(1.0f - dice) + 0.5f*(1.0f - sdice);
        out[1] = dice;
        out[2] = sdice;
    }
    // reset accumulators for the next graph replay (globals start zeroed at
    // module load, so the invariant "g_acc == 0 on entry" always holds)
    #pragma unroll
    for (int v = 0; v < 8; v++) g_acc[i][v] = 0.0f;
}

extern "C" void kernel_launch(void* const* d_in, const int* in_sizes, int n_in,
                              void* d_out, int out_size){
    const float* logits = (const float*)d_in[0];
    const float* target = (const float*)d_in[1];
    float* out = (float*)d_out;

    int nblocks = 2 * NIMG * CTILES * NBANDS;      // 1280 single-warp blocks

    k_skel1<<<nblocks, 32>>>(logits, target);      // iters 1..5 + dice sums
    k_skel2<<<nblocks, 32>>>();                    // iters 6..10
    k_sdice<<<dim3(NIMG, 32), 256>>>();
    k_fin<<<1, 32>>>(out);
    (void)in_sizes; (void)n_in; (void)out_size;
}

// round 9
// speedup vs baseline: 1.2280x; 1.0585x over previous
#include <cuda_runtime.h>

#define HH 512
#define WW 512
#define NPIX (HH*WW)
#define NIMG 32
#define SMOOTHF 1e-5f
#define KF 5            // fused skeletonize iterations per pass
#define HALO_C 12       // column halo per side (>= 2*KF, multiple of 4)
#define OWNC 104        // owned columns per warp window (128 - 2*HALO_C)
#define CTILES 5        // ceil(512/104)
#define RB 128          // rows per band
#define NBANDS 4
#define LAGOUT 14       // output lag: 3*(KF-1)+2
#define NSTEPS 154      // RB + 25 + 1 (even, x0 = r0-11)
#define ALLM 0xffffffffu

// Scratch (device globals: no allocation allowed; zero-initialized at load)
__device__ float g_tmp [2][NIMG*NPIX];   // after iterations 1..5
__device__ float g_skel[2][NIMG*NPIX];   // after iterations 6..10
__device__ float g_acc [NIMG][8];        // 0:sp 1:st 2:spt 3:ssp 4:sst 5:sspt

__device__ __forceinline__ float sigf(float x){
    return __fdividef(1.0f, 1.0f + __expf(-x));
}

// ---------------- dice sums: sigmoid(logits) vs target (MLP-batched) -------
__global__ void k_dice(const float* __restrict__ logits, const float* __restrict__ target){
    int img = blockIdx.x;
    size_t base = (size_t)img*NPIX + (size_t)blockIdx.y*(NPIX/32);
    const float4* Lp = (const float4*)(logits + base);
    const float4* Tp = (const float4*)(target + base);
    int tid = threadIdx.x;
    // batch all 16 independent LDG.128 up front for max MLP
    float4 l[8], t[8];
    #pragma unroll
    for (int i = 0; i < 8; i++) l[i] = Lp[i*256 + tid];
    #pragma unroll
    for (int i = 0; i < 8; i++) t[i] = Tp[i*256 + tid];
    float sp=0.f, st=0.f, spt=0.f;
    #pragma unroll
    for (int i = 0; i < 8; i++){
        float p;
        p = sigf(l[i].x); sp += p; st += t[i].x; spt += p*t[i].x;
        p = sigf(l[i].y); sp += p; st += t[i].y; spt += p*t[i].y;
        p = sigf(l[i].z); sp += p; st += t[i].z; spt += p*t[i].z;
        p = sigf(l[i].w); sp += p; st += t[i].w; spt += p*t[i].w;
    }
    #pragma unroll
    for (int o=16;o;o>>=1){
        sp  += __shfl_down_sync(ALLM, sp , o);
        st  += __shfl_down_sync(ALLM, st , o);
        spt += __shfl_down_sync(ALLM, spt, o);
    }
    if ((tid & 31) == 0){
        atomicAdd(&g_acc[img][0], sp);
        atomicAdd(&g_acc[img][1], st);
        atomicAdd(&g_acc[img][2], spt);
    }
}

// ---------------- skeleton dice sums (MLP-batched) ----------------
__global__ void k_sdice(){
    int img = blockIdx.x;
    size_t base = (size_t)img*NPIX + (size_t)blockIdx.y*(NPIX/32);
    const float4* Pp = (const float4*)(g_skel[0] + base);
    const float4* Tp = (const float4*)(g_skel[1] + base);
    int tid = threadIdx.x;
    float4 p[8], t[8];
    #pragma unroll
    for (int i = 0; i < 8; i++) p[i] = Pp[i*256 + tid];
    #pragma unroll
    for (int i = 0; i < 8; i++) t[i] = Tp[i*256 + tid];
    float sp=0.f, st=0.f, spt=0.f;
    #pragma unroll
    for (int i = 0; i < 8; i++){
        sp  += (p[i].x+p[i].y)+(p[i].z+p[i].w);
        st  += (t[i].x+t[i].y)+(t[i].z+t[i].w);
        spt += (p[i].x*t[i].x + p[i].y*t[i].y) + (p[i].z*t[i].z + p[i].w*t[i].w);
    }
    #pragma unroll
    for (int o=16;o;o>>=1){
        sp  += __shfl_down_sync(ALLM, sp , o);
        st  += __shfl_down_sync(ALLM, st , o);
        spt += __shfl_down_sync(ALLM, spt, o);
    }
    if ((tid & 31) == 0){
        atomicAdd(&g_acc[img][3], sp);
        atomicAdd(&g_acc[img][4], st);
        atomicAdd(&g_acc[img][5], spt);
    }
}

// One decoupled pipeline stage j. Fed row xr = x - 3j (value in CIN).
// State: sN[j] = In_j[xr-1], sO[j] = In_j[xr-2], eN[j] = E_j[xr-2],
// eO[j] = E_j[xr-3]. Computes E_j[xr-1] and O_j[xr-2] -> OUT.
// Rotation by role swap (zero MOVs). Output is NOT boundary-forced: at
// OOB rows/cols it becomes +INF or NaN; fminf/fmaxf drop NaN operands, so
// downstream min chains treat it exactly as the +INF sentinel. Only the
// eroded field needs explicit forcing (en -> -INF at OOB), since it feeds
// a max-pool where the neutral element differs.
#define STAGE(j, sN, sO, eN, eO, CIN, OUT)                                    \
{                                                                             \
    float vm0 = fminf(sO[j][0], fminf(sN[j][0], CIN[0]));                     \
    float vm1 = fminf(sO[j][1], fminf(sN[j][1], CIN[1]));                     \
    float vm2 = fminf(sO[j][2], fminf(sN[j][2], CIN[2]));                     \
    float vm3 = fminf(sO[j][3], fminf(sN[j][3], CIN[3]));                     \
    float Lm = __shfl_up_sync  (ALLM, vm3, 1);                                \
    float Rm = __shfl_down_sync(ALLM, vm0, 1);                                \
    float m01 = fminf(vm0, vm1), m12 = fminf(vm1, vm2), m23 = fminf(vm2, vm3);\
    float en0 = fminf(Lm,  m01);                                              \
    float en1 = fminf(m01, vm2);                                              \
    float en2 = fminf(m12, vm3);                                              \
    float en3 = fminf(m23, Rm);                                               \
    if (!(colok && (unsigned)(x - 3*(j) - 1) < (unsigned)HH)){                \
        en0 = NINF; en1 = NINF; en2 = NINF; en3 = NINF;                       \
    }                                                                         \
    float tx0 = fmaxf(eO[j][0], fmaxf(eN[j][0], en0));                        \
    float tx1 = fmaxf(eO[j][1], fmaxf(eN[j][1], en1));                        \
    float tx2 = fmaxf(eO[j][2], fmaxf(eN[j][2], en2));                        \
    float tx3 = fmaxf(eO[j][3], fmaxf(eN[j][3], en3));                        \
    float Lx = __shfl_up_sync  (ALLM, tx3, 1);                                \
    float Rx = __shfl_down_sync(ALLM, tx0, 1);                                \
    float M01 = fmaxf(tx0, tx1), M12 = fmaxf(tx1, tx2), M23 = fmaxf(tx2, tx3);\
    float T0 = fmaxf(Lx,  M01);                                               \
    float T1 = fmaxf(M01, tx2);                                               \
    float T2 = fmaxf(M12, tx3);                                               \
    float T3 = fmaxf(M23, Rx);                                                \
    float o0 = fmaf(eN[j][0]-sO[j][0], T0, sO[j][0]);                         \
    float o1 = fmaf(eN[j][1]-sO[j][1], T1, sO[j][1]);                         \
    float o2 = fmaf(eN[j][2]-sO[j][2], T2, sO[j][2]);                         \
    float o3 = fmaf(eN[j][3]-sO[j][3], T3, sO[j][3]);                         \
    sO[j][0] = CIN[0]; sO[j][1] = CIN[1]; sO[j][2] = CIN[2]; sO[j][3] = CIN[3];\
    eO[j][0] = en0;    eO[j][1] = en1;    eO[j][2] = en2;    eO[j][3] = en3;  \
    OUT[0] = o0; OUT[1] = o1; OUT[2] = o2; OUT[3] = o3;                       \
}

// One full row-step. Stages evaluated in DESCENDING order so each stage j+1
// reads buf[j] (previous step's output of stage j) before stage j overwrites
// it. All 5 stages are mutually independent within a step -> ILP ~5.
#define DO_STEP(X, sN, sO, eN, eO)                                            \
{                                                                             \
    int x = (X);                                                              \
    float in0[4] = {nxt[0], nxt[1], nxt[2], nxt[3]};                          \
    int xn = x + 1;                                                           \
    if (colok && (unsigned)xn < (unsigned)HH){                                \
        float4 t4 = *(const float4*)(src + (size_t)xn*WW + gc);               \
        if (FIRST && tens == 0){                                              \
            t4.x = sigf(t4.x); t4.y = sigf(t4.y);                             \
            t4.z = sigf(t4.z); t4.w = sigf(t4.w);                             \
        }                                                                     \
        nxt[0]=t4.x; nxt[1]=t4.y; nxt[2]=t4.z; nxt[3]=t4.w;                   \
    } else {                                                                  \
        nxt[0]=PINF; nxt[1]=PINF; nxt[2]=PINF; nxt[3]=PINF;                   \
    }                                                                         \
    float o4[4];                                                              \
    STAGE(4, sN, sO, eN, eO, b3,  o4);                                        \
    STAGE(3, sN, sO, eN, eO, b2,  b3);                                        \
    STAGE(2, sN, sO, eN, eO, b1,  b2);                                        \
    STAGE(1, sN, sO, eN, eO, b0,  b1);                                        \
    STAGE(0, sN, sO, eN, eO, in0, b0);                                        \
    if (owned && (unsigned)(x - LAGOUT - r0) < (unsigned)RB){                 \
        *(float4*)(dst + (size_t)(x - LAGOUT)*WW + gc) =                      \
            make_float4(o4[0], o4[1], o4[2], o4[3]);                          \
    }                                                                         \
}

// ---------------- fused 5-iteration soft skeletonize pass ----------------
// Single-warp blocks for fine-grained SM load balance (1280 blocks / 148 SMs
// -> 9 vs 8 warps per SM instead of 12 vs 8 with 4-warp blocks).
template<bool FIRST>
__global__ void __launch_bounds__(32, 12) k_skel(const float* __restrict__ logits,
                                                 const float* __restrict__ target){
    const float PINF = __int_as_float(0x7f800000);
    const float NINF = __int_as_float(0xff800000);

    int gw   = blockIdx.x;
    int lane = threadIdx.x;
    int band = gw & 3;  int q = gw >> 2;
    int ct   = q % CTILES; q /= CTILES;
    int img  = q & 31;  int tens = q >> 5;

    const float* __restrict__ src;
    float* __restrict__ dst;
    if (FIRST){
        src = (tens ? target : logits) + (size_t)img*NPIX;
        dst = g_tmp[tens] + (size_t)img*NPIX;
    } else {
        src = g_tmp[tens] + (size_t)img*NPIX;
        dst = g_skel[tens] + (size_t)img*NPIX;
    }

    int r0 = band * RB;
    int c0 = ct*OWNC - HALO_C;
    int gc = c0 + (lane<<2);                 // lane's 4 global cols (mult of 4)
    bool colok = (gc >= 0) && (gc < WW);     // whole float4 in or out
    bool owned = (lane >= HALO_C/4) && (lane < (HALO_C+OWNC)/4) && colok;

    // Ping-pong state per stage + one-step output buffers b0..b3
    float sA[KF][4], sB[KF][4], eA[KF][4], eB[KF][4];
    float b0[4], b1[4], b2[4], b3[4];
    #pragma unroll
    for (int j = 0; j < KF; j++)
        #pragma unroll
        for (int v = 0; v < 4; v++){
            sA[j][v]=PINF; sB[j][v]=PINF; eA[j][v]=NINF; eB[j][v]=NINF;
        }
    #pragma unroll
    for (int v = 0; v < 4; v++){ b0[v]=PINF; b1[v]=PINF; b2[v]=PINF; b3[v]=PINF; }

    int x0 = r0 - 11;

    // software-pipelined row fetch: nxt holds the row for the upcoming step
    float nxt[4];
    if (colok && (unsigned)x0 < (unsigned)HH){
        float4 t4 = *(const float4*)(src + (size_t)x0*WW + gc);
        if (FIRST && tens == 0){
            t4.x = sigf(t4.x); t4.y = sigf(t4.y);
            t4.z = sigf(t4.z); t4.w = sigf(t4.w);
        }
        nxt[0]=t4.x; nxt[1]=t4.y; nxt[2]=t4.z; nxt[3]=t4.w;
    } else {
        nxt[0]=PINF; nxt[1]=PINF; nxt[2]=PINF; nxt[3]=PINF;
    }

    for (int step = 0; step < NSTEPS; step += 2){
        DO_STEP(x0 + step,     sA, sB, eA, eB);
        DO_STEP(x0 + step + 1, sB, sA, eB, eA);
    }
}

// ---------------- final reduction (also re-zeroes accumulators) ----------------
__global__ void k_fin(float* __restrict__ out){
    int i = threadIdx.x;   // 32 threads, one per image
    float d  = (2.0f*g_acc[i][2] + SMOOTHF) / (g_acc[i][0] + g_acc[i][1] + SMOOTHF);
    float sd = (2.0f*g_acc[i][5] + SMOOTHF) / (g_acc[i][3] + g_acc[i][4] + SMOOTHF);
    #pragma unroll
    for (int o=16;o;o>>=1){
        d  += __shfl_down_sync(ALLM, d , o);
        sd += __shfl_down_sync(ALLM, sd, o);
    }
    if (i == 0){
        float dice  = d  * (1.0f/32.0f);
        float sdice = sd * (1.0f/32.0f);
        out[0] = 0.5f*(1.0f - dice) + 0.5f*(1.0f - sdice);
        out[1] = dice;
        out[2] = sdice;
    }
    // reset accumulators for the next graph replay (globals start zeroed at
    // module load, so the invariant "g_acc == 0 on entry" always holds)
    #pragma unroll
    for (int v = 0; v < 8; v++) g_acc[i][v] = 0.0f;
}

extern "C" void kernel_launch(void* const* d_in, const int* in_sizes, int n_in,
                              void* d_out, int out_size){
    const float* logits = (const float*)d_in[0];
    const float* target = (const float*)d_in[1];
    float* out = (float*)d_out;

    int nblocks = 2 * NIMG * CTILES * NBANDS;      // 1280 single-warp blocks

    k_dice<<<dim3(NIMG, 32), 256>>>(logits, target);
    k_skel<true ><<<nblocks, 32>>>(logits, target);
    k_skel<false><<<nblocks, 32>>>(logits, target);
    k_sdice<<<dim3(NIMG, 32), 256>>>();
    k_fin<<<1, 32>>>(out);
    (void)in_sizes; (void)n_in; (void)out_size;
}